// round 13
// baseline (speedup 1.0000x reference)
#include <cuda_runtime.h>
#include <cuda_bf16.h>
#include <math.h>
#include <stdint.h>

// ---------------- problem constants ----------------
#define DIMX   96
#define HIDX   384
#define DEPTHX 5
#define HEADSX 8
#define INNERX 6144          // 64 * 96
#define DHX    768           // INNERX / HEADSX
#define BX     2
#define NSEQ   512
#define ROWSX  (BX*NSEQ)     // 1024
#define NQKV   (3*INNERX)    // 18432
#define SCALEX 0.125f
#define EPSX   1e-5f
#define SPLIT_WO 16
#define SPLIT_W2 4
#define STAGES 4
#define A_STG 5120           // bf16 per A stage: 128 rows * 40
#define B_STG 5120
#define B_STGW 2560          // words per B stage
#define SMEM_BYTES (STAGES*(A_STG+B_STG)*2)   // 81920

typedef __nv_bfloat16 bf16;

// pack ranges
#define NQW (15*(DIMX/2)*NQKV)
#define NOW (15*(INNERX/2)*DIMX)
#define N1W (10*(DIMX/2)*HIDX)
#define N2W (10*(HIDX/2)*DIMX)
#define NXC (ROWSX*DIMX)
#define NPACK (NQW+NOW+N1W+N2W+NXC)

// ---------------- scratch (device globals; no allocation allowed) ----------------
__device__ float g_x   [ROWSX*DIMX];
__device__ bf16  g_h   [ROWSX*DIMX];
__device__ bf16  g_qk  [ROWSX*2*INNERX];           // q | k, ld = 2*INNERX
__device__ uint32_t g_v[(ROWSX/2)*INNERX];         // v pair-interleaved [m/2][c] words
__device__ bf16  g_o   [ROWSX*INNERX];
__device__ bf16  g_sim [BX*HEADSX*NSEQ*NSEQ];
__device__ bf16  g_mh  [ROWSX*HIDX];
__device__ float g_part[SPLIT_WO*ROWSX*DIMX];
__device__ uint32_t g_wqkv[15*(DIMX/2)*NQKV];
__device__ uint32_t g_wo  [15*(INNERX/2)*DIMX];
__device__ uint32_t g_w1  [10*(DIMX/2)*HIDX];
__device__ uint32_t g_w2  [10*(HIDX/2)*DIMX];

// ---------------- helpers ----------------
__device__ __forceinline__ void cp16(uint32_t smem_addr, const void* gptr, bool pred) {
    int sz = pred ? 16 : 0;
    asm volatile("cp.async.cg.shared.global [%0], [%1], 16, %2;\n"
                 :: "r"(smem_addr), "l"(gptr), "r"(sz));
}
__device__ __forceinline__ void cp_commit() { asm volatile("cp.async.commit_group;\n"); }
template<int N>
__device__ __forceinline__ void cp_wait() { asm volatile("cp.async.wait_group %0;\n" :: "n"(N)); }

__device__ __forceinline__ void mma_bf16(float& d0, float& d1, float& d2, float& d3,
                                         uint32_t a0, uint32_t a1, uint32_t a2, uint32_t a3,
                                         uint32_t b0, uint32_t b1) {
    asm volatile(
        "mma.sync.aligned.m16n8k16.row.col.f32.bf16.bf16.f32 "
        "{%0,%1,%2,%3}, {%4,%5,%6,%7}, {%8,%9}, {%0,%1,%2,%3};\n"
        : "+f"(d0), "+f"(d1), "+f"(d2), "+f"(d3)
        : "r"(a0), "r"(a1), "r"(a2), "r"(a3), "r"(b0), "r"(b1));
}
__device__ __forceinline__ void ldsm4(uint32_t& r0, uint32_t& r1, uint32_t& r2, uint32_t& r3,
                                      uint32_t addr) {
    asm volatile("ldmatrix.sync.aligned.m8n8.x4.shared.b16 {%0,%1,%2,%3}, [%4];"
        : "=r"(r0), "=r"(r1), "=r"(r2), "=r"(r3) : "r"(addr));
}
__device__ __forceinline__ uint32_t pack2(float lo, float hi) {
    __nv_bfloat162 p = __floats2bfloat162_rn(lo, hi);
    return *(uint32_t*)&p;
}

// ---------------- fused pack kernel: all weights + x copy ----------------
__global__ void pack_all_kernel(const float* __restrict__ Wq, const float* __restrict__ Wk,
                                const float* __restrict__ Wv, const float* __restrict__ Wo,
                                const float* __restrict__ W1, const float* __restrict__ W2,
                                const float* __restrict__ x,
                                uint32_t* __restrict__ dqkv, uint32_t* __restrict__ dwo,
                                uint32_t* __restrict__ dw1,  uint32_t* __restrict__ dw2,
                                float* __restrict__ dx) {
    long i = (long)blockIdx.x * 256 + threadIdx.x;
    if (i >= NPACK) return;
    if (i < NQW) {
        long w = i;
        int n   = (int)(w % NQKV);
        long lkp = w / NQKV;
        const float* S; int c;
        if (n < INNERX)        { S = Wq; c = n; }
        else if (n < 2*INNERX) { S = Wk; c = n - INNERX; }
        else                   { S = Wv; c = n - 2*INNERX; }
        size_t r0 = (size_t)(2*lkp) * INNERX + c;
        dqkv[w] = pack2(S[r0], S[r0 + INNERX]);
    } else if (i < NQW + NOW) {
        long w = i - NQW;
        int n = (int)(w % DIMX);
        long lkp = w / DIMX;
        size_t r0 = (size_t)(2*lkp) * DIMX + n;
        dwo[w] = pack2(Wo[r0], Wo[r0 + DIMX]);
    } else if (i < NQW + NOW + N1W) {
        long w = i - NQW - NOW;
        int n = (int)(w % HIDX);
        long lkp = w / HIDX;
        size_t r0 = (size_t)(2*lkp) * HIDX + n;
        dw1[w] = pack2(W1[r0], W1[r0 + HIDX]);
    } else if (i < NQW + NOW + N1W + N2W) {
        long w = i - NQW - NOW - N1W;
        int n = (int)(w % DIMX);
        long lkp = w / DIMX;
        size_t r0 = (size_t)(2*lkp) * DIMX + n;
        dw2[w] = pack2(W2[r0], W2[r0 + DIMX]);
    } else {
        long w = i - NQW - NOW - N1W - N2W;
        dx[w] = x[w];
    }
}

// ---------------- LayerNorm (dim=96) -> bf16 h ----------------
__global__ void ln_kernel(const float* __restrict__ in, const float* __restrict__ g,
                          bf16* __restrict__ out) {
    int row = blockIdx.x;
    int t   = threadIdx.x;
    __shared__ float s[DIMX];
    __shared__ float red[2];
    float v = in[(size_t)row*DIMX + t];
    s[t] = v;
    __syncthreads();
    float a = 0.f;
    if (t < 32) a = s[t] + s[t+32] + s[t+64];
    #pragma unroll
    for (int o = 16; o > 0; o >>= 1) a += __shfl_down_sync(0xffffffffu, a, o);
    if (t == 0) red[0] = a;
    __syncthreads();
    float mu = red[0] * (1.0f / DIMX);
    float d  = v - mu;
    s[t] = d * d;
    __syncthreads();
    float b = 0.f;
    if (t < 32) b = s[t] + s[t+32] + s[t+64];
    #pragma unroll
    for (int o = 16; o > 0; o >>= 1) b += __shfl_down_sync(0xffffffffu, b, o);
    if (t == 0) red[1] = b;
    __syncthreads();
    float var = red[1] * (1.0f / DIMX);
    out[(size_t)row*DIMX + t] = __float2bfloat16_rn(d * rsqrtf(var + EPSX) * (g[t] + 1.0f));
}

// ---------------- fused split-K reduce + residual + LayerNorm ----------------
template<bool BFOUT, bool HASBIAS>
__global__ void red_ln_kernel(const float* __restrict__ part, int S,
                              const float* __restrict__ bias,
                              float* __restrict__ x, const float* __restrict__ g,
                              void* __restrict__ outp) {
    const int MN = ROWSX * DIMX;
    int row = blockIdx.x;
    int t   = threadIdx.x;
    size_t idx = (size_t)row*DIMX + t;
    float val = x[idx];
    if (HASBIAS) val += bias[t];
    for (int s = 0; s < S; s++) val += part[(size_t)s*MN + idx];
    __shared__ float sm[DIMX];
    __shared__ float red[2];
    sm[t] = val;
    __syncthreads();
    float a = 0.f;
    if (t < 32) a = sm[t] + sm[t+32] + sm[t+64];
    #pragma unroll
    for (int o = 16; o > 0; o >>= 1) a += __shfl_down_sync(0xffffffffu, a, o);
    if (t == 0) red[0] = a;
    __syncthreads();
    float mu = red[0] * (1.0f / DIMX);
    float d  = val - mu;
    sm[t] = d * d;
    __syncthreads();
    float b = 0.f;
    if (t < 32) b = sm[t] + sm[t+32] + sm[t+64];
    #pragma unroll
    for (int o = 16; o > 0; o >>= 1) b += __shfl_down_sync(0xffffffffu, b, o);
    if (t == 0) red[1] = b;
    __syncthreads();
    float var = red[1] * (1.0f / DIMX);
    float lnv = d * rsqrtf(var + EPSX) * (g[t] + 1.0f);
    x[idx] = val;
    if (BFOUT) ((bf16*)outp)[idx] = __float2bfloat16_rn(lnv);
    else       ((float*)outp)[idx] = lnv;
}

// ---------------- fused: reduce + bare mid-LN (replaces x) + MLP pre-norm -> h ----------------
__global__ void red_ln_mid_kernel(const float* __restrict__ part, int S,
                                  float* __restrict__ x,
                                  const float* __restrict__ g1,   // gam_mid
                                  const float* __restrict__ g2,   // gam_m (mlp pre-norm)
                                  bf16* __restrict__ h) {
    const int MN = ROWSX * DIMX;
    int row = blockIdx.x;
    int t   = threadIdx.x;
    size_t idx = (size_t)row*DIMX + t;
    float val = x[idx];
    for (int s = 0; s < S; s++) val += part[(size_t)s*MN + idx];
    __shared__ float sm[DIMX];
    __shared__ float red[4];
    // ---- LN1 (bare mid-LN)
    sm[t] = val;
    __syncthreads();
    float a = 0.f;
    if (t < 32) a = sm[t] + sm[t+32] + sm[t+64];
    #pragma unroll
    for (int o = 16; o > 0; o >>= 1) a += __shfl_down_sync(0xffffffffu, a, o);
    if (t == 0) red[0] = a;
    __syncthreads();
    float mu = red[0] * (1.0f / DIMX);
    float d  = val - mu;
    sm[t] = d * d;
    __syncthreads();
    float b = 0.f;
    if (t < 32) b = sm[t] + sm[t+32] + sm[t+64];
    #pragma unroll
    for (int o = 16; o > 0; o >>= 1) b += __shfl_down_sync(0xffffffffu, b, o);
    if (t == 0) red[1] = b;
    __syncthreads();
    float var = red[1] * (1.0f / DIMX);
    float ln1 = d * rsqrtf(var + EPSX) * (g1[t] + 1.0f);
    x[idx] = ln1;
    // ---- LN2 (MLP pre-norm) on ln1
    __syncthreads();
    sm[t] = ln1;
    __syncthreads();
    float a2 = 0.f;
    if (t < 32) a2 = sm[t] + sm[t+32] + sm[t+64];
    #pragma unroll
    for (int o = 16; o > 0; o >>= 1) a2 += __shfl_down_sync(0xffffffffu, a2, o);
    if (t == 0) red[2] = a2;
    __syncthreads();
    float mu2 = red[2] * (1.0f / DIMX);
    float d2  = ln1 - mu2;
    sm[t] = d2 * d2;
    __syncthreads();
    float b2s = 0.f;
    if (t < 32) b2s = sm[t] + sm[t+32] + sm[t+64];
    #pragma unroll
    for (int o = 16; o > 0; o >>= 1) b2s += __shfl_down_sync(0xffffffffu, b2s, o);
    if (t == 0) red[3] = b2s;
    __syncthreads();
    float var2 = red[3] * (1.0f / DIMX);
    h[idx] = __float2bfloat16_rn(d2 * rsqrtf(var2 + EPSX) * (g2[t] + 1.0f));
}

// ---------------- row softmax over 512 cols (bf16 in/out, fp32 math) ----------------
__global__ void softmax_kernel(bf16* __restrict__ sim) {
    int row = blockIdx.x;
    bf16* p = sim + (size_t)row * NSEQ;
    int t = threadIdx.x;                    // 256
    float a = __bfloat162float(p[t]), b = __bfloat162float(p[t + 256]);
    __shared__ float s[256];
    s[t] = fmaxf(a, b);
    __syncthreads();
    for (int o = 128; o >= 32; o >>= 1) { if (t < o) s[t] = fmaxf(s[t], s[t+o]); __syncthreads(); }
    if (t < 32) {
        float x = s[t];
        #pragma unroll
        for (int o = 16; o > 0; o >>= 1) x = fmaxf(x, __shfl_down_sync(0xffffffffu, x, o));
        if (t == 0) s[0] = x;
    }
    __syncthreads();
    float m = s[0];
    __syncthreads();
    float ea = expf(a - m), eb = expf(b - m);
    s[t] = ea + eb;
    __syncthreads();
    for (int o = 128; o >= 32; o >>= 1) { if (t < o) s[t] += s[t+o]; __syncthreads(); }
    if (t < 32) {
        float x = s[t];
        #pragma unroll
        for (int o = 16; o > 0; o >>= 1) x += __shfl_down_sync(0xffffffffu, x, o);
        if (t == 0) s[0] = x;
    }
    __syncthreads();
    float inv = 1.0f / s[0];
    p[t]       = __float2bfloat16_rn(ea * inv);
    p[t + 256] = __float2bfloat16_rn(eb * inv);
}

// ---------------- bf16 tensor-core GEMM, 4-stage cp.async, ldmatrix frags ----------------
// 128x128 block, BK=32, 256 threads, warp tile 64x32, m16n8k16.
// A: row-major bf16 [M,K]; B NN: pair-interleaved words [K/2][N];
// B TRANSB: row-major bf16 [N,K]. OUT: 0 fp32, 1 bf16, 2 QKV (qk bf16 + v interleaved).
template<bool TRANSB, bool BIAS, bool GELU, bool SPLIT, int OUT>
__global__ __launch_bounds__(256, 2)
void mma_gemm(const bf16* __restrict__ A, const void* __restrict__ Bm,
              const float* __restrict__ bias, void* __restrict__ Cp,
              uint32_t* __restrict__ Cv,
              int M, int Nn, int K_len,
              int lda, int ldb, int ldc,
              long sA_b, long sA_h, long sB_b, long sB_h, long sC_b, long sC_h,
              long splitStride, float alpha) {
    extern __shared__ bf16 smem[];
    bf16* Asm = smem;                      // [STAGES][128][40]
    bf16* Bsm = smem + STAGES*A_STG;

    const int tid = threadIdx.x;
    const int bz  = blockIdx.z;
    const bf16* Ab; const void* Bb;
    long coff;
    int kbase;
    if (SPLIT) {
        Ab = A; Bb = Bm;
        coff = (long)bz * splitStride;
        kbase = bz * K_len;
    } else {
        long bb = bz >> 3, hh = bz & 7;
        Ab = A + bb * sA_b + hh * sA_h;
        if (TRANSB) Bb = (const void*)((const bf16*)Bm + bb * sB_b + hh * sB_h);
        else        Bb = (const void*)((const uint32_t*)Bm + bb * sB_b + hh * sB_h);
        coff = bb * sC_b + hh * sC_h;
        kbase = 0;
    }

    const int bm = blockIdx.y * 128;
    const int bn = blockIdx.x * 128;
    const int wid = tid >> 5;
    const int lane = tid & 31;
    const int gid = lane >> 2;
    const int tg  = lane & 3;
    const int wm = (wid & 1) * 64;
    const int wn = (wid >> 1) * 32;

    const uint32_t as0 = (uint32_t)__cvta_generic_to_shared(Asm);
    const uint32_t bs0 = (uint32_t)__cvta_generic_to_shared(Bsm);

    const int laneArow = lane & 15;
    const int laneAk   = (lane >> 4) * 8;

    const int nt = K_len / 32;

    float acc[4][4][4];
    #pragma unroll
    for (int mi = 0; mi < 4; mi++)
        #pragma unroll
        for (int ni = 0; ni < 4; ni++)
            #pragma unroll
            for (int r = 0; r < 4; r++) acc[mi][ni][r] = 0.f;

    auto load_tile = [&](int t, int s) {
        const int kpos = kbase + t * 32;
        #pragma unroll
        for (int r = 0; r < 2; r++) {
            int idx = tid + 256 * r;
            int row = idx >> 2;
            int kc  = (idx & 3) * 8;
            const bf16* src = Ab + (size_t)(bm + row) * lda + kpos + kc;
            cp16(as0 + (s * A_STG + row * 40 + kc) * 2, src, true);
        }
        if (!TRANSB) {
            const uint32_t* Bw = (const uint32_t*)Bb;
            int kp0 = kpos >> 1;
            #pragma unroll
            for (int r = 0; r < 2; r++) {
                int idx = tid + 256 * r;
                int wrow = idx >> 5;
                int wc   = (idx & 31) * 4;
                const uint32_t* src = Bw + (size_t)(kp0 + wrow) * ldb + bn + wc;
                cp16(bs0 + (s * B_STGW + wrow * 136 + wc) * 4, src, (bn + wc) < Nn);
            }
        } else {
            const bf16* Bt = (const bf16*)Bb;
            #pragma unroll
            for (int r = 0; r < 2; r++) {
                int idx = tid + 256 * r;
                int row = idx >> 2;
                int kc  = (idx & 3) * 8;
                const bf16* src = Bt + (size_t)(bn + row) * ldb + kpos + kc;
                cp16(bs0 + (s * A_STG + row * 40 + kc) * 2, src, (bn + row) < Nn);
            }
        }
        cp_commit();
    };

    #pragma unroll
    for (int s = 0; s < STAGES - 1; s++)
        if (s < nt) load_tile(s, s);

    for (int t = 0; t < nt; t++) {
        const int cur = t & 3;
        if (t + 3 <= nt)      cp_wait<2>();
        else if (t + 2 <= nt) cp_wait<1>();
        else                  cp_wait<0>();
        __syncthreads();
        if (t + 3 < nt) load_tile(t + 3, (t + 3) & 3);

        const uint32_t aBase = as0 + cur * A_STG * 2;
        const bf16* bt = Bsm + cur * A_STG;
        const uint32_t* bw = (const uint32_t*)Bsm + cur * B_STGW;

        #pragma unroll
        for (int s = 0; s < 32; s += 16) {
            uint32_t bf[4][2];
            if (!TRANSB) {
                #pragma unroll
                for (int ni = 0; ni < 4; ni++) {
                    int ncol = wn + ni * 8 + gid;
                    bf[ni][0] = bw[((s >> 1) + tg    ) * 136 + ncol];
                    bf[ni][1] = bw[((s >> 1) + tg + 4) * 136 + ncol];
                }
            } else {
                #pragma unroll
                for (int ni = 0; ni < 4; ni++) {
                    bf[ni][0] = *(const uint32_t*)(bt + (wn + ni*8 + gid) * 40 + s + 2*tg);
                    bf[ni][1] = *(const uint32_t*)(bt + (wn + ni*8 + gid) * 40 + s + 2*tg + 8);
                }
            }
            #pragma unroll
            for (int mi = 0; mi < 4; mi++) {
                uint32_t a0, a1, a2, a3;
                uint32_t addr = aBase + ((wm + mi*16 + laneArow) * 40 + s + laneAk) * 2;
                ldsm4(a0, a1, a2, a3, addr);
                #pragma unroll
                for (int ni = 0; ni < 4; ni++)
                    mma_bf16(acc[mi][ni][0], acc[mi][ni][1], acc[mi][ni][2], acc[mi][ni][3],
                             a0, a1, a2, a3, bf[ni][0], bf[ni][1]);
            }
        }
    }

    #pragma unroll
    for (int mi = 0; mi < 4; mi++) {
        int m0 = bm + wm + mi * 16 + gid;
        #pragma unroll
        for (int ni = 0; ni < 4; ni++) {
            int n0 = bn + wn + ni * 8 + tg * 2;
            #pragma unroll
            for (int rr = 0; rr < 2; rr++) {
                int m = m0 + rr * 8;
                #pragma unroll
                for (int cc = 0; cc < 2; cc++) {
                    int n = n0 + cc;
                    if (n < Nn) {
                        float v = acc[mi][ni][rr * 2 + cc] * alpha;
                        if (BIAS) v += bias[n];
                        if (GELU) v = 0.5f * v * (1.0f + erff(v * 0.70710678118654752f));
                        if (OUT == 0) {
                            ((float*)Cp)[coff + (size_t)m * ldc + n] = v;
                        } else if (OUT == 1) {
                            ((bf16*)Cp)[coff + (size_t)m * ldc + n] = __float2bfloat16_rn(v);
                        } else {
                            if (n < 2*INNERX) {
                                ((bf16*)Cp)[coff + (size_t)m * ldc + n] = __float2bfloat16_rn(v);
                            } else {
                                int c = n - 2*INNERX;
                                size_t vi = ((size_t)(m >> 1) * INNERX + c) * 2 + (m & 1);
                                ((bf16*)Cv)[vi] = __float2bfloat16_rn(v);
                            }
                        }
                    }
                }
            }
        }
    }
}

// ---------------- host orchestration ----------------
extern "C" void kernel_launch(void* const* d_in, const int* in_sizes, int n_in,
                              void* d_out, int out_size) {
    const float* x         = (const float*)d_in[0];
    const float* gam_a     = (const float*)d_in[1];
    const float* Wq        = (const float*)d_in[2];
    const float* Wk        = (const float*)d_in[3];
    const float* Wv        = (const float*)d_in[4];
    const float* Wo        = (const float*)d_in[5];
    const float* gam_m     = (const float*)d_in[6];
    const float* W1        = (const float*)d_in[7];
    const float* b1        = (const float*)d_in[8];
    const float* W2        = (const float*)d_in[9];
    const float* b2        = (const float*)d_in[10];
    const float* gam_mid   = (const float*)d_in[11];
    const float* gam_final = (const float*)d_in[12];
    float* out = (float*)d_out;

    float *px, *ppart;
    bf16 *ph, *pqk, *po, *psim, *pmh;
    uint32_t *pv, *pwqkv, *pwo, *pw1, *pw2;
    cudaGetSymbolAddress((void**)&px,    g_x);
    cudaGetSymbolAddress((void**)&ph,    g_h);
    cudaGetSymbolAddress((void**)&pqk,   g_qk);
    cudaGetSymbolAddress((void**)&pv,    g_v);
    cudaGetSymbolAddress((void**)&po,    g_o);
    cudaGetSymbolAddress((void**)&psim,  g_sim);
    cudaGetSymbolAddress((void**)&pmh,   g_mh);
    cudaGetSymbolAddress((void**)&ppart, g_part);
    cudaGetSymbolAddress((void**)&pwqkv, g_wqkv);
    cudaGetSymbolAddress((void**)&pwo,   g_wo);
    cudaGetSymbolAddress((void**)&pw1,   g_w1);
    cudaGetSymbolAddress((void**)&pw2,   g_w2);

    cudaFuncSetAttribute(mma_gemm<false,false,false,false,2>,
                         cudaFuncAttributeMaxDynamicSharedMemorySize, SMEM_BYTES);
    cudaFuncSetAttribute(mma_gemm<true,false,false,false,1>,
                         cudaFuncAttributeMaxDynamicSharedMemorySize, SMEM_BYTES);
    cudaFuncSetAttribute(mma_gemm<false,false,false,false,1>,
                         cudaFuncAttributeMaxDynamicSharedMemorySize, SMEM_BYTES);
    cudaFuncSetAttribute(mma_gemm<false,false,false,true,0>,
                         cudaFuncAttributeMaxDynamicSharedMemorySize, SMEM_BYTES);
    cudaFuncSetAttribute(mma_gemm<false,true,true,false,1>,
                         cudaFuncAttributeMaxDynamicSharedMemorySize, SMEM_BYTES);

    // ---- fused weight packing + x copy (one node) ----
    pack_all_kernel<<<(unsigned)((NPACK + 255)/256), 256>>>(
        Wq, Wk, Wv, Wo, W1, W2, x, pwqkv, pwo, pw1, pw2, px);

    // first attention pre-norm
    ln_kernel<<<ROWSX, DIMX>>>(px, gam_a + 0, ph);

    const long sQK_b  = (long)NSEQ * 2*INNERX;
    const long sQK_h  = (long)DHX;
    const long sSIM_h = (long)NSEQ * NSEQ;
    const long sSIM_b = sSIM_h * HEADSX;
    const long sV_b   = (long)(NSEQ/2) * INNERX;   // v words
    const long sV_h   = (long)DHX;
    const long sO_b   = (long)NSEQ * INNERX;
    const long sO_h   = (long)DHX;

    auto do_attn = [&](int widx) {
        const uint32_t* wqkv_l = pwqkv + (size_t)widx * (DIMX/2) * NQKV;
        const uint32_t* wo_l   = pwo   + (size_t)widx * (INNERX/2) * DIMX;
        // fused QKV: q,k -> pqk; v -> interleaved pv
        mma_gemm<false,false,false,false,2><<<dim3(NQKV/128, ROWSX/128, 1), 256, SMEM_BYTES>>>(
            ph, wqkv_l, nullptr, pqk, pv, ROWSX, NQKV, DIMX, DIMX, NQKV, 2*INNERX,
            0,0,0,0,0,0, 0, 1.0f);
        // scores = SCALE * q @ k^T per (b,h)
        mma_gemm<true,false,false,false,1><<<dim3(NSEQ/128, NSEQ/128, BX*HEADSX), 256, SMEM_BYTES>>>(
            pqk, pqk + INNERX, nullptr, psim, nullptr, NSEQ, NSEQ, DHX,
            2*INNERX, 2*INNERX, NSEQ,
            sQK_b, sQK_h, sQK_b, sQK_h, sSIM_b, sSIM_h, 0, SCALEX);
        softmax_kernel<<<BX*HEADSX*NSEQ, 256>>>(psim);
        // context = a @ v per (b,h)
        mma_gemm<false,false,false,false,1><<<dim3(DHX/128, NSEQ/128, BX*HEADSX), 256, SMEM_BYTES>>>(
            psim, pv, nullptr, po, nullptr, NSEQ, DHX, NSEQ,
            NSEQ, INNERX /*words*/, INNERX,
            sSIM_b, sSIM_h, sV_b, sV_h, sO_b, sO_h, 0, 1.0f);
        // Wo split-K partials (fp32)
        mma_gemm<false,false,false,true,0><<<dim3(1, ROWSX/128, SPLIT_WO), 256, SMEM_BYTES>>>(
            po, wo_l, nullptr, ppart, nullptr, ROWSX, DIMX, INNERX/SPLIT_WO,
            INNERX, DIMX /*words*/, DIMX,
            0,0,0,0,0,0, (long)ROWSX*DIMX, 1.0f);
    };
    auto do_mlp_gemms = [&](int midx) {
        const uint32_t* w1_l = pw1 + (size_t)midx * (DIMX/2) * HIDX;
        const uint32_t* w2_l = pw2 + (size_t)midx * (HIDX/2) * DIMX;
        mma_gemm<false,true,true,false,1><<<dim3(HIDX/128, ROWSX/128, 1), 256, SMEM_BYTES>>>(
            ph, w1_l, b1 + (size_t)midx * HIDX, pmh, nullptr, ROWSX, HIDX, DIMX,
            DIMX, HIDX /*words*/, HIDX,
            0,0,0,0,0,0, 0, 1.0f);
        mma_gemm<false,false,false,true,0><<<dim3(1, ROWSX/128, SPLIT_W2), 256, SMEM_BYTES>>>(
            pmh, w2_l, nullptr, ppart, nullptr, ROWSX, DIMX, HIDX/SPLIT_W2,
            HIDX, DIMX /*words*/, DIMX,
            0,0,0,0,0,0, (long)ROWSX*DIMX, 1.0f);
    };

    for (int d = 0; d < DEPTHX; d++) {
        do_attn(3*d + 0);
        red_ln_kernel<true,false><<<ROWSX, DIMX>>>(
            ppart, SPLIT_WO, nullptr, px, gam_m + (size_t)(2*d+0)*DIMX, ph);
        do_mlp_gemms(2*d + 0);
        red_ln_kernel<true,true><<<ROWSX, DIMX>>>(
            ppart, SPLIT_W2, b2 + (size_t)(2*d+0)*DIMX, px, gam_a + (size_t)(3*d+1)*DIMX, ph);
        do_attn(3*d + 1);
        red_ln_kernel<true,false><<<ROWSX, DIMX>>>(
            ppart, SPLIT_WO, nullptr, px, gam_a + (size_t)(3*d+2)*DIMX, ph);
        do_attn(3*d + 2);
        // fused: reduce + bare mid-LN + MLP pre-norm
        red_ln_mid_kernel<<<ROWSX, DIMX>>>(
            ppart, SPLIT_WO, px, gam_mid + (size_t)d*DIMX, gam_m + (size_t)(2*d+1)*DIMX, ph);
        do_mlp_gemms(2*d + 1);
        if (d < DEPTHX - 1) {
            red_ln_kernel<true,true><<<ROWSX, DIMX>>>(
                ppart, SPLIT_W2, b2 + (size_t)(2*d+1)*DIMX, px, gam_a + (size_t)(3*d+3)*DIMX, ph);
        } else {
            red_ln_kernel<false,true><<<ROWSX, DIMX>>>(
                ppart, SPLIT_W2, b2 + (size_t)(2*d+1)*DIMX, px, gam_final, out);
        }
    }
}

// round 15
// speedup vs baseline: 1.0058x; 1.0058x over previous
#include <cuda_runtime.h>
#include <cuda_bf16.h>
#include <math.h>
#include <stdint.h>

// ---------------- problem constants ----------------
#define DIMX   96
#define HIDX   384
#define DEPTHX 5
#define HEADSX 8
#define INNERX 6144          // 64 * 96
#define DHX    768           // INNERX / HEADSX
#define BX     2
#define NSEQ   512
#define ROWSX  (BX*NSEQ)     // 1024
#define NQKV   (3*INNERX)    // 18432
#define SCALEX 0.125f
#define EPSX   1e-5f
#define SPLIT_WO 16
#define SPLIT_W2 4
#define STAGES 4
#define A_STG 5120           // bf16 per A stage: 128 rows * 40
#define B_STG 2560           // bf16 per B stage: TRANSB 64*40; NN 16*72 words = 1152w <= 1280w
#define B_STGW 1280          // words per B stage
#define SMEM_BYTES (STAGES*(A_STG+B_STG)*2)   // 61440

typedef __nv_bfloat16 bf16;

// pack ranges
#define NQW (15*(DIMX/2)*NQKV)
#define NOW (15*(INNERX/2)*DIMX)
#define N1W (10*(DIMX/2)*HIDX)
#define N2W (10*(HIDX/2)*DIMX)
#define NXC (ROWSX*DIMX)
#define NPACK (NQW+NOW+N1W+N2W+NXC)

// ---------------- scratch (device globals; no allocation allowed) ----------------
__device__ float g_x   [ROWSX*DIMX];
__device__ bf16  g_h   [ROWSX*DIMX];
__device__ bf16  g_qk  [ROWSX*2*INNERX];           // q | k, ld = 2*INNERX
__device__ uint32_t g_v[(ROWSX/2)*INNERX];         // v pair-interleaved [m/2][c] words
__device__ bf16  g_o   [ROWSX*INNERX];
__device__ bf16  g_sim [BX*HEADSX*NSEQ*NSEQ];
__device__ bf16  g_mh  [ROWSX*HIDX];
__device__ float g_part[SPLIT_WO*ROWSX*DIMX];
__device__ uint32_t g_wqkv[15*(DIMX/2)*NQKV];
__device__ uint32_t g_wo  [15*(INNERX/2)*DIMX];
__device__ uint32_t g_w1  [10*(DIMX/2)*HIDX];
__device__ uint32_t g_w2  [10*(HIDX/2)*DIMX];

// ---------------- helpers ----------------
__device__ __forceinline__ void cp16(uint32_t smem_addr, const void* gptr, bool pred) {
    int sz = pred ? 16 : 0;
    asm volatile("cp.async.cg.shared.global [%0], [%1], 16, %2;\n"
                 :: "r"(smem_addr), "l"(gptr), "r"(sz));
}
__device__ __forceinline__ void cp_commit() { asm volatile("cp.async.commit_group;\n"); }
template<int N>
__device__ __forceinline__ void cp_wait() { asm volatile("cp.async.wait_group %0;\n" :: "n"(N)); }

__device__ __forceinline__ void mma_bf16(float& d0, float& d1, float& d2, float& d3,
                                         uint32_t a0, uint32_t a1, uint32_t a2, uint32_t a3,
                                         uint32_t b0, uint32_t b1) {
    asm volatile(
        "mma.sync.aligned.m16n8k16.row.col.f32.bf16.bf16.f32 "
        "{%0,%1,%2,%3}, {%4,%5,%6,%7}, {%8,%9}, {%0,%1,%2,%3};\n"
        : "+f"(d0), "+f"(d1), "+f"(d2), "+f"(d3)
        : "r"(a0), "r"(a1), "r"(a2), "r"(a3), "r"(b0), "r"(b1));
}
__device__ __forceinline__ void ldsm4(uint32_t& r0, uint32_t& r1, uint32_t& r2, uint32_t& r3,
                                      uint32_t addr) {
    asm volatile("ldmatrix.sync.aligned.m8n8.x4.shared.b16 {%0,%1,%2,%3}, [%4];"
        : "=r"(r0), "=r"(r1), "=r"(r2), "=r"(r3) : "r"(addr));
}
__device__ __forceinline__ uint32_t pack2(float lo, float hi) {
    __nv_bfloat162 p = __floats2bfloat162_rn(lo, hi);
    return *(uint32_t*)&p;
}

// ---------------- fused pack kernel: all weights + x copy ----------------
__global__ void pack_all_kernel(const float* __restrict__ Wq, const float* __restrict__ Wk,
                                const float* __restrict__ Wv, const float* __restrict__ Wo,
                                const float* __restrict__ W1, const float* __restrict__ W2,
                                const float* __restrict__ x,
                                uint32_t* __restrict__ dqkv, uint32_t* __restrict__ dwo,
                                uint32_t* __restrict__ dw1,  uint32_t* __restrict__ dw2,
                                float* __restrict__ dx) {
    long i = (long)blockIdx.x * 256 + threadIdx.x;
    if (i >= NPACK) return;
    if (i < NQW) {
        long w = i;
        int n   = (int)(w % NQKV);
        long lkp = w / NQKV;
        const float* S; int c;
        if (n < INNERX)        { S = Wq; c = n; }
        else if (n < 2*INNERX) { S = Wk; c = n - INNERX; }
        else                   { S = Wv; c = n - 2*INNERX; }
        size_t r0 = (size_t)(2*lkp) * INNERX + c;
        dqkv[w] = pack2(S[r0], S[r0 + INNERX]);
    } else if (i < NQW + NOW) {
        long w = i - NQW;
        int n = (int)(w % DIMX);
        long lkp = w / DIMX;
        size_t r0 = (size_t)(2*lkp) * DIMX + n;
        dwo[w] = pack2(Wo[r0], Wo[r0 + DIMX]);
    } else if (i < NQW + NOW + N1W) {
        long w = i - NQW - NOW;
        int n = (int)(w % HIDX);
        long lkp = w / HIDX;
        size_t r0 = (size_t)(2*lkp) * HIDX + n;
        dw1[w] = pack2(W1[r0], W1[r0 + HIDX]);
    } else if (i < NQW + NOW + N1W + N2W) {
        long w = i - NQW - NOW - N1W;
        int n = (int)(w % DIMX);
        long lkp = w / DIMX;
        size_t r0 = (size_t)(2*lkp) * DIMX + n;
        dw2[w] = pack2(W2[r0], W2[r0 + DIMX]);
    } else {
        long w = i - NQW - NOW - N1W - N2W;
        dx[w] = x[w];
    }
}

// ---------------- LayerNorm (dim=96) -> bf16 h ----------------
__global__ void ln_kernel(const float* __restrict__ in, const float* __restrict__ g,
                          bf16* __restrict__ out) {
    int row = blockIdx.x;
    int t   = threadIdx.x;
    __shared__ float s[DIMX];
    __shared__ float red[2];
    float v = in[(size_t)row*DIMX + t];
    s[t] = v;
    __syncthreads();
    float a = 0.f;
    if (t < 32) a = s[t] + s[t+32] + s[t+64];
    #pragma unroll
    for (int o = 16; o > 0; o >>= 1) a += __shfl_down_sync(0xffffffffu, a, o);
    if (t == 0) red[0] = a;
    __syncthreads();
    float mu = red[0] * (1.0f / DIMX);
    float d  = v - mu;
    s[t] = d * d;
    __syncthreads();
    float b = 0.f;
    if (t < 32) b = s[t] + s[t+32] + s[t+64];
    #pragma unroll
    for (int o = 16; o > 0; o >>= 1) b += __shfl_down_sync(0xffffffffu, b, o);
    if (t == 0) red[1] = b;
    __syncthreads();
    float var = red[1] * (1.0f / DIMX);
    out[(size_t)row*DIMX + t] = __float2bfloat16_rn(d * rsqrtf(var + EPSX) * (g[t] + 1.0f));
}

// ---------------- fused split-K reduce + residual + LayerNorm ----------------
template<bool BFOUT, bool HASBIAS>
__global__ void red_ln_kernel(const float* __restrict__ part, int S,
                              const float* __restrict__ bias,
                              float* __restrict__ x, const float* __restrict__ g,
                              void* __restrict__ outp) {
    const int MN = ROWSX * DIMX;
    int row = blockIdx.x;
    int t   = threadIdx.x;
    size_t idx = (size_t)row*DIMX + t;
    float val = x[idx];
    if (HASBIAS) val += bias[t];
    for (int s = 0; s < S; s++) val += part[(size_t)s*MN + idx];
    __shared__ float sm[DIMX];
    __shared__ float red[2];
    sm[t] = val;
    __syncthreads();
    float a = 0.f;
    if (t < 32) a = sm[t] + sm[t+32] + sm[t+64];
    #pragma unroll
    for (int o = 16; o > 0; o >>= 1) a += __shfl_down_sync(0xffffffffu, a, o);
    if (t == 0) red[0] = a;
    __syncthreads();
    float mu = red[0] * (1.0f / DIMX);
    float d  = val - mu;
    sm[t] = d * d;
    __syncthreads();
    float b = 0.f;
    if (t < 32) b = sm[t] + sm[t+32] + sm[t+64];
    #pragma unroll
    for (int o = 16; o > 0; o >>= 1) b += __shfl_down_sync(0xffffffffu, b, o);
    if (t == 0) red[1] = b;
    __syncthreads();
    float var = red[1] * (1.0f / DIMX);
    float lnv = d * rsqrtf(var + EPSX) * (g[t] + 1.0f);
    x[idx] = val;
    if (BFOUT) ((bf16*)outp)[idx] = __float2bfloat16_rn(lnv);
    else       ((float*)outp)[idx] = lnv;
}

// ---------------- fused: reduce + bare mid-LN (replaces x) + MLP pre-norm -> h ----------------
__global__ void red_ln_mid_kernel(const float* __restrict__ part, int S,
                                  float* __restrict__ x,
                                  const float* __restrict__ g1,   // gam_mid
                                  const float* __restrict__ g2,   // gam_m (mlp pre-norm)
                                  bf16* __restrict__ h) {
    const int MN = ROWSX * DIMX;
    int row = blockIdx.x;
    int t   = threadIdx.x;
    size_t idx = (size_t)row*DIMX + t;
    float val = x[idx];
    for (int s = 0; s < S; s++) val += part[(size_t)s*MN + idx];
    __shared__ float sm[DIMX];
    __shared__ float red[4];
    // ---- LN1 (bare mid-LN)
    sm[t] = val;
    __syncthreads();
    float a = 0.f;
    if (t < 32) a = sm[t] + sm[t+32] + sm[t+64];
    #pragma unroll
    for (int o = 16; o > 0; o >>= 1) a += __shfl_down_sync(0xffffffffu, a, o);
    if (t == 0) red[0] = a;
    __syncthreads();
    float mu = red[0] * (1.0f / DIMX);
    float d  = val - mu;
    sm[t] = d * d;
    __syncthreads();
    float b = 0.f;
    if (t < 32) b = sm[t] + sm[t+32] + sm[t+64];
    #pragma unroll
    for (int o = 16; o > 0; o >>= 1) b += __shfl_down_sync(0xffffffffu, b, o);
    if (t == 0) red[1] = b;
    __syncthreads();
    float var = red[1] * (1.0f / DIMX);
    float ln1 = d * rsqrtf(var + EPSX) * (g1[t] + 1.0f);
    x[idx] = ln1;
    // ---- LN2 (MLP pre-norm) on ln1
    __syncthreads();
    sm[t] = ln1;
    __syncthreads();
    float a2 = 0.f;
    if (t < 32) a2 = sm[t] + sm[t+32] + sm[t+64];
    #pragma unroll
    for (int o = 16; o > 0; o >>= 1) a2 += __shfl_down_sync(0xffffffffu, a2, o);
    if (t == 0) red[2] = a2;
    __syncthreads();
    float mu2 = red[2] * (1.0f / DIMX);
    float d2  = ln1 - mu2;
    sm[t] = d2 * d2;
    __syncthreads();
    float b2s = 0.f;
    if (t < 32) b2s = sm[t] + sm[t+32] + sm[t+64];
    #pragma unroll
    for (int o = 16; o > 0; o >>= 1) b2s += __shfl_down_sync(0xffffffffu, b2s, o);
    if (t == 0) red[3] = b2s;
    __syncthreads();
    float var2 = red[3] * (1.0f / DIMX);
    h[idx] = __float2bfloat16_rn(d2 * rsqrtf(var2 + EPSX) * (g2[t] + 1.0f));
}

// ---------------- row softmax over 512 cols (bf16 in/out, fp32 math) ----------------
__global__ void softmax_kernel(bf16* __restrict__ sim) {
    int row = blockIdx.x;
    bf16* p = sim + (size_t)row * NSEQ;
    int t = threadIdx.x;                    // 256
    float a = __bfloat162float(p[t]), b = __bfloat162float(p[t + 256]);
    __shared__ float s[256];
    s[t] = fmaxf(a, b);
    __syncthreads();
    for (int o = 128; o >= 32; o >>= 1) { if (t < o) s[t] = fmaxf(s[t], s[t+o]); __syncthreads(); }
    if (t < 32) {
        float x = s[t];
        #pragma unroll
        for (int o = 16; o > 0; o >>= 1) x = fmaxf(x, __shfl_down_sync(0xffffffffu, x, o));
        if (t == 0) s[0] = x;
    }
    __syncthreads();
    float m = s[0];
    __syncthreads();
    float ea = expf(a - m), eb = expf(b - m);
    s[t] = ea + eb;
    __syncthreads();
    for (int o = 128; o >= 32; o >>= 1) { if (t < o) s[t] += s[t+o]; __syncthreads(); }
    if (t < 32) {
        float x = s[t];
        #pragma unroll
        for (int o = 16; o > 0; o >>= 1) x += __shfl_down_sync(0xffffffffu, x, o);
        if (t == 0) s[0] = x;
    }
    __syncthreads();
    float inv = 1.0f / s[0];
    p[t]       = __float2bfloat16_rn(ea * inv);
    p[t + 256] = __float2bfloat16_rn(eb * inv);
}

// ---------------- bf16 tensor-core GEMM, 4-stage cp.async, 128x64 tile ----------------
// CTA tile 128x64, BK=32, 256 threads = 8 warps (4 along M x 2 along N),
// warp tile 32x32 (mi 2 x ni 4), m16n8k16. 32 acc regs -> 3 CTAs/SM.
// A: row-major bf16 [M,K]; B NN: pair-interleaved words [K/2][N];
// B TRANSB: row-major bf16 [N,K]. OUT: 0 fp32, 1 bf16, 2 QKV (qk bf16 + v interleaved).
template<bool TRANSB, bool BIAS, bool GELU, bool SPLIT, int OUT>
__global__ __launch_bounds__(256, 3)
void mma_gemm(const bf16* __restrict__ A, const void* __restrict__ Bm,
              const float* __restrict__ bias, void* __restrict__ Cp,
              uint32_t* __restrict__ Cv,
              int M, int Nn, int K_len,
              int lda, int ldb, int ldc,
              long sA_b, long sA_h, long sB_b, long sB_h, long sC_b, long sC_h,
              long splitStride, float alpha) {
    extern __shared__ bf16 smem[];
    bf16* Asm = smem;                      // [STAGES][128][40]
    bf16* Bsm = smem + STAGES*A_STG;       // TRANSB: [64][40] ; NN: [16][72] words

    const int tid = threadIdx.x;
    const int bz  = blockIdx.z;
    const bf16* Ab; const void* Bb;
    long coff;
    int kbase;
    if (SPLIT) {
        Ab = A; Bb = Bm;
        coff = (long)bz * splitStride;
        kbase = bz * K_len;
    } else {
        long bb = bz >> 3, hh = bz & 7;
        Ab = A + bb * sA_b + hh * sA_h;
        if (TRANSB) Bb = (const void*)((const bf16*)Bm + bb * sB_b + hh * sB_h);
        else        Bb = (const void*)((const uint32_t*)Bm + bb * sB_b + hh * sB_h);
        coff = bb * sC_b + hh * sC_h;
        kbase = 0;
    }

    const int bm = blockIdx.y * 128;
    const int bn = blockIdx.x * 64;
    const int wid = tid >> 5;
    const int lane = tid & 31;
    const int gid = lane >> 2;
    const int tg  = lane & 3;
    const int wm = (wid & 3) * 32;         // 4 warps along M
    const int wn = (wid >> 2) * 32;        // 2 warps along N

    const uint32_t as0 = (uint32_t)__cvta_generic_to_shared(Asm);
    const uint32_t bs0 = (uint32_t)__cvta_generic_to_shared(Bsm);

    const int laneArow = lane & 15;
    const int laneAk   = (lane >> 4) * 8;

    const int nt = K_len / 32;

    float acc[2][4][4];
    #pragma unroll
    for (int mi = 0; mi < 2; mi++)
        #pragma unroll
        for (int ni = 0; ni < 4; ni++)
            #pragma unroll
            for (int r = 0; r < 4; r++) acc[mi][ni][r] = 0.f;

    auto load_tile = [&](int t, int s) {
        const int kpos = kbase + t * 32;
        // A: 128 rows x 32 bf16 -> 512 cp16, 2 per thread
        #pragma unroll
        for (int r = 0; r < 2; r++) {
            int idx = tid + 256 * r;
            int row = idx >> 2;
            int kc  = (idx & 3) * 8;
            const bf16* src = Ab + (size_t)(bm + row) * lda + kpos + kc;
            cp16(as0 + (s * A_STG + row * 40 + kc) * 2, src, true);
        }
        if (!TRANSB) {
            // B: 16 pair-rows x 64 words -> 256 cp16, 1 per thread
            const uint32_t* Bw = (const uint32_t*)Bb;
            int kp0 = kpos >> 1;
            int wrow = tid >> 4;
            int wc   = (tid & 15) * 4;
            const uint32_t* src = Bw + (size_t)(kp0 + wrow) * ldb + bn + wc;
            cp16(bs0 + (s * B_STGW + wrow * 72 + wc) * 4, src, (bn + wc) < Nn);
        } else {
            // B: 64 rows x 32 bf16 -> 256 cp16, 1 per thread
            const bf16* Bt = (const bf16*)Bb;
            int row = tid >> 2;
            int kc  = (tid & 3) * 8;
            const bf16* src = Bt + (size_t)(bn + row) * ldb + kpos + kc;
            cp16(bs0 + (s * B_STG + row * 40 + kc) * 2, src, (bn + row) < Nn);
        }
        cp_commit();
    };

    #pragma unroll
    for (int s = 0; s < STAGES - 1; s++)
        if (s < nt) load_tile(s, s);

    for (int t = 0; t < nt; t++) {
        const int cur = t & 3;
        if (t + 3 <= nt)      cp_wait<2>();
        else if (t + 2 <= nt) cp_wait<1>();
        else                  cp_wait<0>();
        __syncthreads();
        if (t + 3 < nt) load_tile(t + 3, (t + 3) & 3);

        const uint32_t aBase = as0 + cur * A_STG * 2;
        const bf16* bt = Bsm + cur * B_STG;
        const uint32_t* bw = (const uint32_t*)Bsm + cur * B_STGW;

        #pragma unroll
        for (int s = 0; s < 32; s += 16) {
            uint32_t bf[4][2];
            if (!TRANSB) {
                #pragma unroll
                for (int ni = 0; ni < 4; ni++) {
                    int ncol = wn + ni * 8 + gid;
                    bf[ni][0] = bw[((s >> 1) + tg    ) * 72 + ncol];
                    bf[ni][1] = bw[((s >> 1) + tg + 4) * 72 + ncol];
                }
            } else {
                #pragma unroll
                for (int ni = 0; ni < 4; ni++) {
                    bf[ni][0] = *(const uint32_t*)(bt + (wn + ni*8 + gid) * 40 + s + 2*tg);
                    bf[ni][1] = *(const uint32_t*)(bt + (wn + ni*8 + gid) * 40 + s + 2*tg + 8);
                }
            }
            #pragma unroll
            for (int mi = 0; mi < 2; mi++) {
                uint32_t a0, a1, a2, a3;
                uint32_t addr = aBase + ((wm + mi*16 + laneArow) * 40 + s + laneAk) * 2;
                ldsm4(a0, a1, a2, a3, addr);
                #pragma unroll
                for (int ni = 0; ni < 4; ni++)
                    mma_bf16(acc[mi][ni][0], acc[mi][ni][1], acc[mi][ni][2], acc[mi][ni][3],
                             a0, a1, a2, a3, bf[ni][0], bf[ni][1]);
            }
        }
    }

    #pragma unroll
    for (int mi = 0; mi < 2; mi++) {
        int m0 = bm + wm + mi * 16 + gid;
        #pragma unroll
        for (int ni = 0; ni < 4; ni++) {
            int n0 = bn + wn + ni * 8 + tg * 2;
            #pragma unroll
            for (int rr = 0; rr < 2; rr++) {
                int m = m0 + rr * 8;
                #pragma unroll
                for (int cc = 0; cc < 2; cc++) {
                    int n = n0 + cc;
                    if (n < Nn) {
                        float v = acc[mi][ni][rr * 2 + cc] * alpha;
                        if (BIAS) v += bias[n];
                        if (GELU) v = 0.5f * v * (1.0f + erff(v * 0.70710678118654752f));
                        if (OUT == 0) {
                            ((float*)Cp)[coff + (size_t)m * ldc + n] = v;
                        } else if (OUT == 1) {
                            ((bf16*)Cp)[coff + (size_t)m * ldc + n] = __float2bfloat16_rn(v);
                        } else {
                            if (n < 2*INNERX) {
                                ((bf16*)Cp)[coff + (size_t)m * ldc + n] = __float2bfloat16_rn(v);
                            } else {
                                int c = n - 2*INNERX;
                                size_t vi = ((size_t)(m >> 1) * INNERX + c) * 2 + (m & 1);
                                ((bf16*)Cv)[vi] = __float2bfloat16_rn(v);
                            }
                        }
                    }
                }
            }
        }
    }
}

// ---------------- host orchestration ----------------
extern "C" void kernel_launch(void* const* d_in, const int* in_sizes, int n_in,
                              void* d_out, int out_size) {
    const float* x         = (const float*)d_in[0];
    const float* gam_a     = (const float*)d_in[1];
    const float* Wq        = (const float*)d_in[2];
    const float* Wk        = (const float*)d_in[3];
    const float* Wv        = (const float*)d_in[4];
    const float* Wo        = (const float*)d_in[5];
    const float* gam_m     = (const float*)d_in[6];
    const float* W1        = (const float*)d_in[7];
    const float* b1        = (const float*)d_in[8];
    const float* W2        = (const float*)d_in[9];
    const float* b2        = (const float*)d_in[10];
    const float* gam_mid   = (const float*)d_in[11];
    const float* gam_final = (const float*)d_in[12];
    float* out = (float*)d_out;

    float *px, *ppart;
    bf16 *ph, *pqk, *po, *psim, *pmh;
    uint32_t *pv, *pwqkv, *pwo, *pw1, *pw2;
    cudaGetSymbolAddress((void**)&px,    g_x);
    cudaGetSymbolAddress((void**)&ph,    g_h);
    cudaGetSymbolAddress((void**)&pqk,   g_qk);
    cudaGetSymbolAddress((void**)&pv,    g_v);
    cudaGetSymbolAddress((void**)&po,    g_o);
    cudaGetSymbolAddress((void**)&psim,  g_sim);
    cudaGetSymbolAddress((void**)&pmh,   g_mh);
    cudaGetSymbolAddress((void**)&ppart, g_part);
    cudaGetSymbolAddress((void**)&pwqkv, g_wqkv);
    cudaGetSymbolAddress((void**)&pwo,   g_wo);
    cudaGetSymbolAddress((void**)&pw1,   g_w1);
    cudaGetSymbolAddress((void**)&pw2,   g_w2);

    cudaFuncSetAttribute(mma_gemm<false,false,false,false,2>,
                         cudaFuncAttributeMaxDynamicSharedMemorySize, SMEM_BYTES);
    cudaFuncSetAttribute(mma_gemm<true,false,false,false,1>,
                         cudaFuncAttributeMaxDynamicSharedMemorySize, SMEM_BYTES);
    cudaFuncSetAttribute(mma_gemm<false,false,false,false,1>,
                         cudaFuncAttributeMaxDynamicSharedMemorySize, SMEM_BYTES);
    cudaFuncSetAttribute(mma_gemm<false,false,false,true,0>,
                         cudaFuncAttributeMaxDynamicSharedMemorySize, SMEM_BYTES);
    cudaFuncSetAttribute(mma_gemm<false,true,true,false,1>,
                         cudaFuncAttributeMaxDynamicSharedMemorySize, SMEM_BYTES);

    // ---- fused weight packing + x copy (one node) ----
    pack_all_kernel<<<(unsigned)((NPACK + 255)/256), 256>>>(
        Wq, Wk, Wv, Wo, W1, W2, x, pwqkv, pwo, pw1, pw2, px);

    // first attention pre-norm
    ln_kernel<<<ROWSX, DIMX>>>(px, gam_a + 0, ph);

    const long sQK_b  = (long)NSEQ * 2*INNERX;
    const long sQK_h  = (long)DHX;
    const long sSIM_h = (long)NSEQ * NSEQ;
    const long sSIM_b = sSIM_h * HEADSX;
    const long sV_b   = (long)(NSEQ/2) * INNERX;   // v words
    const long sV_h   = (long)DHX;
    const long sO_b   = (long)NSEQ * INNERX;
    const long sO_h   = (long)DHX;

    auto do_attn = [&](int widx) {
        const uint32_t* wqkv_l = pwqkv + (size_t)widx * (DIMX/2) * NQKV;
        const uint32_t* wo_l   = pwo   + (size_t)widx * (INNERX/2) * DIMX;
        // fused QKV: q,k -> pqk; v -> interleaved pv
        mma_gemm<false,false,false,false,2><<<dim3(NQKV/64, ROWSX/128, 1), 256, SMEM_BYTES>>>(
            ph, wqkv_l, nullptr, pqk, pv, ROWSX, NQKV, DIMX, DIMX, NQKV, 2*INNERX,
            0,0,0,0,0,0, 0, 1.0f);
        // scores = SCALE * q @ k^T per (b,h)
        mma_gemm<true,false,false,false,1><<<dim3(NSEQ/64, NSEQ/128, BX*HEADSX), 256, SMEM_BYTES>>>(
            pqk, pqk + INNERX, nullptr, psim, nullptr, NSEQ, NSEQ, DHX,
            2*INNERX, 2*INNERX, NSEQ,
            sQK_b, sQK_h, sQK_b, sQK_h, sSIM_b, sSIM_h, 0, SCALEX);
        softmax_kernel<<<BX*HEADSX*NSEQ, 256>>>(psim);
        // context = a @ v per (b,h)
        mma_gemm<false,false,false,false,1><<<dim3(DHX/64, NSEQ/128, BX*HEADSX), 256, SMEM_BYTES>>>(
            psim, pv, nullptr, po, nullptr, NSEQ, DHX, NSEQ,
            NSEQ, INNERX /*words*/, INNERX,
            sSIM_b, sSIM_h, sV_b, sV_h, sO_b, sO_h, 0, 1.0f);
        // Wo split-K partials (fp32), N=96 -> 2 n-tiles
        mma_gemm<false,false,false,true,0><<<dim3(2, ROWSX/128, SPLIT_WO), 256, SMEM_BYTES>>>(
            po, wo_l, nullptr, ppart, nullptr, ROWSX, DIMX, INNERX/SPLIT_WO,
            INNERX, DIMX /*words*/, DIMX,
            0,0,0,0,0,0, (long)ROWSX*DIMX, 1.0f);
    };
    auto do_mlp_gemms = [&](int midx) {
        const uint32_t* w1_l = pw1 + (size_t)midx * (DIMX/2) * HIDX;
        const uint32_t* w2_l = pw2 + (size_t)midx * (HIDX/2) * DIMX;
        mma_gemm<false,true,true,false,1><<<dim3(HIDX/64, ROWSX/128, 1), 256, SMEM_BYTES>>>(
            ph, w1_l, b1 + (size_t)midx * HIDX, pmh, nullptr, ROWSX, HIDX, DIMX,
            DIMX, HIDX /*words*/, HIDX,
            0,0,0,0,0,0, 0, 1.0f);
        mma_gemm<false,false,false,true,0><<<dim3(2, ROWSX/128, SPLIT_W2), 256, SMEM_BYTES>>>(
            pmh, w2_l, nullptr, ppart, nullptr, ROWSX, DIMX, HIDX/SPLIT_W2,
            HIDX, DIMX /*words*/, DIMX,
            0,0,0,0,0,0, (long)ROWSX*DIMX, 1.0f);
    };

    for (int d = 0; d < DEPTHX; d++) {
        do_attn(3*d + 0);
        red_ln_kernel<true,false><<<ROWSX, DIMX>>>(
            ppart, SPLIT_WO, nullptr, px, gam_m + (size_t)(2*d+0)*DIMX, ph);
        do_mlp_gemms(2*d + 0);
        red_ln_kernel<true,true><<<ROWSX, DIMX>>>(
            ppart, SPLIT_W2, b2 + (size_t)(2*d+0)*DIMX, px, gam_a + (size_t)(3*d+1)*DIMX, ph);
        do_attn(3*d + 1);
        red_ln_kernel<true,false><<<ROWSX, DIMX>>>(
            ppart, SPLIT_WO, nullptr, px, gam_a + (size_t)(3*d+2)*DIMX, ph);
        do_attn(3*d + 2);
        // fused: reduce + bare mid-LN + MLP pre-norm
        red_ln_mid_kernel<<<ROWSX, DIMX>>>(
            ppart, SPLIT_WO, px, gam_mid + (size_t)d*DIMX, gam_m + (size_t)(2*d+1)*DIMX, ph);
        do_mlp_gemms(2*d + 1);
        if (d < DEPTHX - 1) {
            red_ln_kernel<true,true><<<ROWSX, DIMX>>>(
                ppart, SPLIT_W2, b2 + (size_t)(2*d+1)*DIMX, px, gam_a + (size_t)(3*d+3)*DIMX, ph);
        } else {
            red_ln_kernel<false,true><<<ROWSX, DIMX>>>(
                ppart, SPLIT_W2, b2 + (size_t)(2*d+1)*DIMX, px, gam_final, out);
        }
    }
}

// round 17
// speedup vs baseline: 1.0728x; 1.0666x over previous
#include <cuda_runtime.h>
#include <cuda_bf16.h>
#include <math.h>
#include <stdint.h>

// ---------------- problem constants ----------------
#define DIMX   96
#define HIDX   384
#define DEPTHX 5
#define HEADSX 8
#define INNERX 6144          // 64 * 96
#define DHX    768           // INNERX / HEADSX
#define BX     2
#define NSEQ   512
#define ROWSX  (BX*NSEQ)     // 1024
#define NQKV   (3*INNERX)    // 18432
#define SCALEX 0.125f
#define EPSX   1e-5f
#define SPLIT_WO 16
#define SPLIT_W2 4
#define STAGES 4
#define A_STG 5120           // bf16 per A stage: 128 rows * 40
#define B_STG 2560           // bf16 per B stage: TRANSB 64*40; NN 16*72 words
#define B_STGW 1280          // words per B stage
#define SMEM_BYTES (STAGES*(A_STG+B_STG)*2)   // 61440
#define NRSUM (BX*HEADSX*NSEQ)                // 8192 rows

typedef __nv_bfloat16 bf16;

// pack ranges
#define NQW (15*(DIMX/2)*NQKV)
#define NOW (15*(INNERX/2)*DIMX)
#define N1W (10*(DIMX/2)*HIDX)
#define N2W (10*(HIDX/2)*DIMX)
#define NXC (ROWSX*DIMX)
#define NPACK (NQW+NOW+N1W+N2W+NXC)

// ---------------- scratch (device globals; no allocation allowed) ----------------
__device__ float g_x   [ROWSX*DIMX];
__device__ bf16  g_h   [ROWSX*DIMX];
__device__ bf16  g_qk  [ROWSX*2*INNERX];           // q | k, ld = 2*INNERX
__device__ uint32_t g_v[(ROWSX/2)*INNERX];         // v pair-interleaved [m/2][c] words
__device__ bf16  g_o   [ROWSX*INNERX];
__device__ bf16  g_sim [BX*HEADSX*NSEQ*NSEQ];      // holds exp(sim) after scores
__device__ bf16  g_mh  [ROWSX*HIDX];
__device__ float g_part[SPLIT_WO*ROWSX*DIMX];
__device__ float g_rsum[NRSUM];                    // softmax denominators
__device__ uint32_t g_wqkv[15*(DIMX/2)*NQKV];
__device__ uint32_t g_wo  [15*(INNERX/2)*DIMX];
__device__ uint32_t g_w1  [10*(DIMX/2)*HIDX];
__device__ uint32_t g_w2  [10*(HIDX/2)*DIMX];

// ---------------- helpers ----------------
__device__ __forceinline__ void cp16(uint32_t smem_addr, const void* gptr, bool pred) {
    int sz = pred ? 16 : 0;
    asm volatile("cp.async.cg.shared.global [%0], [%1], 16, %2;\n"
                 :: "r"(smem_addr), "l"(gptr), "r"(sz));
}
__device__ __forceinline__ void cp_commit() { asm volatile("cp.async.commit_group;\n"); }
template<int N>
__device__ __forceinline__ void cp_wait() { asm volatile("cp.async.wait_group %0;\n" :: "n"(N)); }

__device__ __forceinline__ void mma_bf16(float& d0, float& d1, float& d2, float& d3,
                                         uint32_t a0, uint32_t a1, uint32_t a2, uint32_t a3,
                                         uint32_t b0, uint32_t b1) {
    asm volatile(
        "mma.sync.aligned.m16n8k16.row.col.f32.bf16.bf16.f32 "
        "{%0,%1,%2,%3}, {%4,%5,%6,%7}, {%8,%9}, {%0,%1,%2,%3};\n"
        : "+f"(d0), "+f"(d1), "+f"(d2), "+f"(d3)
        : "r"(a0), "r"(a1), "r"(a2), "r"(a3), "r"(b0), "r"(b1));
}
__device__ __forceinline__ void ldsm4(uint32_t& r0, uint32_t& r1, uint32_t& r2, uint32_t& r3,
                                      uint32_t addr) {
    asm volatile("ldmatrix.sync.aligned.m8n8.x4.shared.b16 {%0,%1,%2,%3}, [%4];"
        : "=r"(r0), "=r"(r1), "=r"(r2), "=r"(r3) : "r"(addr));
}
__device__ __forceinline__ uint32_t pack2(float lo, float hi) {
    __nv_bfloat162 p = __floats2bfloat162_rn(lo, hi);
    return *(uint32_t*)&p;
}

// ---------------- fused pack kernel: all weights + x copy ----------------
__global__ void pack_all_kernel(const float* __restrict__ Wq, const float* __restrict__ Wk,
                                const float* __restrict__ Wv, const float* __restrict__ Wo,
                                const float* __restrict__ W1, const float* __restrict__ W2,
                                const float* __restrict__ x,
                                uint32_t* __restrict__ dqkv, uint32_t* __restrict__ dwo,
                                uint32_t* __restrict__ dw1,  uint32_t* __restrict__ dw2,
                                float* __restrict__ dx) {
    long i = (long)blockIdx.x * 256 + threadIdx.x;
    if (i >= NPACK) return;
    if (i < NQW) {
        long w = i;
        int n   = (int)(w % NQKV);
        long lkp = w / NQKV;
        const float* S; int c;
        if (n < INNERX)        { S = Wq; c = n; }
        else if (n < 2*INNERX) { S = Wk; c = n - INNERX; }
        else                   { S = Wv; c = n - 2*INNERX; }
        size_t r0 = (size_t)(2*lkp) * INNERX + c;
        dqkv[w] = pack2(S[r0], S[r0 + INNERX]);
    } else if (i < NQW + NOW) {
        long w = i - NQW;
        int n = (int)(w % DIMX);
        long lkp = w / DIMX;
        size_t r0 = (size_t)(2*lkp) * DIMX + n;
        dwo[w] = pack2(Wo[r0], Wo[r0 + DIMX]);
    } else if (i < NQW + NOW + N1W) {
        long w = i - NQW - NOW;
        int n = (int)(w % HIDX);
        long lkp = w / HIDX;
        size_t r0 = (size_t)(2*lkp) * HIDX + n;
        dw1[w] = pack2(W1[r0], W1[r0 + HIDX]);
    } else if (i < NQW + NOW + N1W + N2W) {
        long w = i - NQW - NOW - N1W;
        int n = (int)(w % DIMX);
        long lkp = w / DIMX;
        size_t r0 = (size_t)(2*lkp) * DIMX + n;
        dw2[w] = pack2(W2[r0], W2[r0 + DIMX]);
    } else {
        long w = i - NQW - NOW - N1W - N2W;
        dx[w] = x[w];
    }
}

// ---------------- zero helper: each of 1024 row-blocks clears 8 rsum slots ----------------
__device__ __forceinline__ void zero_rsum(int row, int t) {
    if (t < 8) g_rsum[row * 8 + t] = 0.f;
}

// ---------------- LayerNorm (dim=96) -> bf16 h (+ rsum zero) ----------------
__global__ void ln_kernel(const float* __restrict__ in, const float* __restrict__ g,
                          bf16* __restrict__ out) {
    int row = blockIdx.x;
    int t   = threadIdx.x;
    zero_rsum(row, t);
    __shared__ float s[DIMX];
    __shared__ float red[2];
    float v = in[(size_t)row*DIMX + t];
    s[t] = v;
    __syncthreads();
    float a = 0.f;
    if (t < 32) a = s[t] + s[t+32] + s[t+64];
    #pragma unroll
    for (int o = 16; o > 0; o >>= 1) a += __shfl_down_sync(0xffffffffu, a, o);
    if (t == 0) red[0] = a;
    __syncthreads();
    float mu = red[0] * (1.0f / DIMX);
    float d  = v - mu;
    s[t] = d * d;
    __syncthreads();
    float b = 0.f;
    if (t < 32) b = s[t] + s[t+32] + s[t+64];
    #pragma unroll
    for (int o = 16; o > 0; o >>= 1) b += __shfl_down_sync(0xffffffffu, b, o);
    if (t == 0) red[1] = b;
    __syncthreads();
    float var = red[1] * (1.0f / DIMX);
    out[(size_t)row*DIMX + t] = __float2bfloat16_rn(d * rsqrtf(var + EPSX) * (g[t] + 1.0f));
}

// ---------------- fused split-K reduce + residual + LayerNorm (+ rsum zero) ----------------
template<bool BFOUT, bool HASBIAS>
__global__ void red_ln_kernel(const float* __restrict__ part, int S,
                              const float* __restrict__ bias,
                              float* __restrict__ x, const float* __restrict__ g,
                              void* __restrict__ outp) {
    const int MN = ROWSX * DIMX;
    int row = blockIdx.x;
    int t   = threadIdx.x;
    if (BFOUT) zero_rsum(row, t);
    size_t idx = (size_t)row*DIMX + t;
    float val = x[idx];
    if (HASBIAS) val += bias[t];
    for (int s = 0; s < S; s++) val += part[(size_t)s*MN + idx];
    __shared__ float sm[DIMX];
    __shared__ float red[2];
    sm[t] = val;
    __syncthreads();
    float a = 0.f;
    if (t < 32) a = sm[t] + sm[t+32] + sm[t+64];
    #pragma unroll
    for (int o = 16; o > 0; o >>= 1) a += __shfl_down_sync(0xffffffffu, a, o);
    if (t == 0) red[0] = a;
    __syncthreads();
    float mu = red[0] * (1.0f / DIMX);
    float d  = val - mu;
    sm[t] = d * d;
    __syncthreads();
    float b = 0.f;
    if (t < 32) b = sm[t] + sm[t+32] + sm[t+64];
    #pragma unroll
    for (int o = 16; o > 0; o >>= 1) b += __shfl_down_sync(0xffffffffu, b, o);
    if (t == 0) red[1] = b;
    __syncthreads();
    float var = red[1] * (1.0f / DIMX);
    float lnv = d * rsqrtf(var + EPSX) * (g[t] + 1.0f);
    x[idx] = val;
    if (BFOUT) ((bf16*)outp)[idx] = __float2bfloat16_rn(lnv);
    else       ((float*)outp)[idx] = lnv;
}

// ---------------- fused: reduce + bare mid-LN (replaces x) + MLP pre-norm -> h ----------------
__global__ void red_ln_mid_kernel(const float* __restrict__ part, int S,
                                  float* __restrict__ x,
                                  const float* __restrict__ g1,   // gam_mid
                                  const float* __restrict__ g2,   // gam_m (mlp pre-norm)
                                  bf16* __restrict__ h) {
    const int MN = ROWSX * DIMX;
    int row = blockIdx.x;
    int t   = threadIdx.x;
    size_t idx = (size_t)row*DIMX + t;
    float val = x[idx];
    for (int s = 0; s < S; s++) val += part[(size_t)s*MN + idx];
    __shared__ float sm[DIMX];
    __shared__ float red[4];
    // ---- LN1 (bare mid-LN)
    sm[t] = val;
    __syncthreads();
    float a = 0.f;
    if (t < 32) a = sm[t] + sm[t+32] + sm[t+64];
    #pragma unroll
    for (int o = 16; o > 0; o >>= 1) a += __shfl_down_sync(0xffffffffu, a, o);
    if (t == 0) red[0] = a;
    __syncthreads();
    float mu = red[0] * (1.0f / DIMX);
    float d  = val - mu;
    sm[t] = d * d;
    __syncthreads();
    float b = 0.f;
    if (t < 32) b = sm[t] + sm[t+32] + sm[t+64];
    #pragma unroll
    for (int o = 16; o > 0; o >>= 1) b += __shfl_down_sync(0xffffffffu, b, o);
    if (t == 0) red[1] = b;
    __syncthreads();
    float var = red[1] * (1.0f / DIMX);
    float ln1 = d * rsqrtf(var + EPSX) * (g1[t] + 1.0f);
    x[idx] = ln1;
    // ---- LN2 (MLP pre-norm) on ln1
    __syncthreads();
    sm[t] = ln1;
    __syncthreads();
    float a2 = 0.f;
    if (t < 32) a2 = sm[t] + sm[t+32] + sm[t+64];
    #pragma unroll
    for (int o = 16; o > 0; o >>= 1) a2 += __shfl_down_sync(0xffffffffu, a2, o);
    if (t == 0) red[2] = a2;
    __syncthreads();
    float mu2 = red[2] * (1.0f / DIMX);
    float d2  = ln1 - mu2;
    sm[t] = d2 * d2;
    __syncthreads();
    float b2s = 0.f;
    if (t < 32) b2s = sm[t] + sm[t+32] + sm[t+64];
    #pragma unroll
    for (int o = 16; o > 0; o >>= 1) b2s += __shfl_down_sync(0xffffffffu, b2s, o);
    if (t == 0) red[3] = b2s;
    __syncthreads();
    float var2 = red[3] * (1.0f / DIMX);
    h[idx] = __float2bfloat16_rn(d2 * rsqrtf(var2 + EPSX) * (g2[t] + 1.0f));
}

// ---------------- bf16 tensor-core GEMM, 4-stage cp.async, 128x64 tile ----------------
// CTA tile 128x64, BK=32, 256 threads = 8 warps (4 M x 2 N), warp tile 32x32.
// OUT: 0 fp32 (split partials), 1 bf16, 2 QKV (qk bf16 + v interleaved),
//      3 scores (exp + rowsum atomics into Cv=rsum), 4 context (divide by rsum=Cv).
template<bool TRANSB, bool BIAS, bool GELU, bool SPLIT, int OUT>
__global__ __launch_bounds__(256, 3)
void mma_gemm(const bf16* __restrict__ A, const void* __restrict__ Bm,
              const float* __restrict__ bias, void* __restrict__ Cp,
              uint32_t* __restrict__ Cv,
              int M, int Nn, int K_len,
              int lda, int ldb, int ldc,
              long sA_b, long sA_h, long sB_b, long sB_h, long sC_b, long sC_h,
              long splitStride, float alpha) {
    extern __shared__ bf16 smem[];
    bf16* Asm = smem;                      // [STAGES][128][40]
    bf16* Bsm = smem + STAGES*A_STG;       // TRANSB: [64][40] ; NN: [16][72] words

    const int tid = threadIdx.x;
    const int bz  = blockIdx.z;
    const bf16* Ab; const void* Bb;
    long coff;
    int kbase;
    if (SPLIT) {
        Ab = A; Bb = Bm;
        coff = (long)bz * splitStride;
        kbase = bz * K_len;
    } else {
        long bb = bz >> 3, hh = bz & 7;
        Ab = A + bb * sA_b + hh * sA_h;
        if (TRANSB) Bb = (const void*)((const bf16*)Bm + bb * sB_b + hh * sB_h);
        else        Bb = (const void*)((const uint32_t*)Bm + bb * sB_b + hh * sB_h);
        coff = bb * sC_b + hh * sC_h;
        kbase = 0;
    }

    const int bm = blockIdx.y * 128;
    const int bn = blockIdx.x * 64;
    const int wid = tid >> 5;
    const int lane = tid & 31;
    const int gid = lane >> 2;
    const int tg  = lane & 3;
    const int wm = (wid & 3) * 32;
    const int wn = (wid >> 2) * 32;

    const uint32_t as0 = (uint32_t)__cvta_generic_to_shared(Asm);
    const uint32_t bs0 = (uint32_t)__cvta_generic_to_shared(Bsm);

    const int laneArow = lane & 15;
    const int laneAk   = (lane >> 4) * 8;

    const int nt = K_len / 32;

    float acc[2][4][4];
    #pragma unroll
    for (int mi = 0; mi < 2; mi++)
        #pragma unroll
        for (int ni = 0; ni < 4; ni++)
            #pragma unroll
            for (int r = 0; r < 4; r++) acc[mi][ni][r] = 0.f;

    auto load_tile = [&](int t, int s) {
        const int kpos = kbase + t * 32;
        #pragma unroll
        for (int r = 0; r < 2; r++) {
            int idx = tid + 256 * r;
            int row = idx >> 2;
            int kc  = (idx & 3) * 8;
            const bf16* src = Ab + (size_t)(bm + row) * lda + kpos + kc;
            cp16(as0 + (s * A_STG + row * 40 + kc) * 2, src, true);
        }
        if (!TRANSB) {
            const uint32_t* Bw = (const uint32_t*)Bb;
            int kp0 = kpos >> 1;
            int wrow = tid >> 4;
            int wc   = (tid & 15) * 4;
            const uint32_t* src = Bw + (size_t)(kp0 + wrow) * ldb + bn + wc;
            cp16(bs0 + (s * B_STGW + wrow * 72 + wc) * 4, src, (bn + wc) < Nn);
        } else {
            const bf16* Bt = (const bf16*)Bb;
            int row = tid >> 2;
            int kc  = (tid & 3) * 8;
            const bf16* src = Bt + (size_t)(bn + row) * ldb + kpos + kc;
            cp16(bs0 + (s * B_STG + row * 40 + kc) * 2, src, (bn + row) < Nn);
        }
        cp_commit();
    };

    #pragma unroll
    for (int s = 0; s < STAGES - 1; s++)
        if (s < nt) load_tile(s, s);

    for (int t = 0; t < nt; t++) {
        const int cur = t & 3;
        if (t + 3 <= nt)      cp_wait<2>();
        else if (t + 2 <= nt) cp_wait<1>();
        else                  cp_wait<0>();
        __syncthreads();
        if (t + 3 < nt) load_tile(t + 3, (t + 3) & 3);

        const uint32_t aBase = as0 + cur * A_STG * 2;
        const bf16* bt = Bsm + cur * B_STG;
        const uint32_t* bw = (const uint32_t*)Bsm + cur * B_STGW;

        #pragma unroll
        for (int s = 0; s < 32; s += 16) {
            uint32_t bf[4][2];
            if (!TRANSB) {
                #pragma unroll
                for (int ni = 0; ni < 4; ni++) {
                    int ncol = wn + ni * 8 + gid;
                    bf[ni][0] = bw[((s >> 1) + tg    ) * 72 + ncol];
                    bf[ni][1] = bw[((s >> 1) + tg + 4) * 72 + ncol];
                }
            } else {
                #pragma unroll
                for (int ni = 0; ni < 4; ni++) {
                    bf[ni][0] = *(const uint32_t*)(bt + (wn + ni*8 + gid) * 40 + s + 2*tg);
                    bf[ni][1] = *(const uint32_t*)(bt + (wn + ni*8 + gid) * 40 + s + 2*tg + 8);
                }
            }
            #pragma unroll
            for (int mi = 0; mi < 2; mi++) {
                uint32_t a0, a1, a2, a3;
                uint32_t addr = aBase + ((wm + mi*16 + laneArow) * 40 + s + laneAk) * 2;
                ldsm4(a0, a1, a2, a3, addr);
                #pragma unroll
                for (int ni = 0; ni < 4; ni++)
                    mma_bf16(acc[mi][ni][0], acc[mi][ni][1], acc[mi][ni][2], acc[mi][ni][3],
                             a0, a1, a2, a3, bf[ni][0], bf[ni][1]);
            }
        }
    }

    // ---- epilogue
    #pragma unroll
    for (int mi = 0; mi < 2; mi++) {
        #pragma unroll
        for (int rr = 0; rr < 2; rr++) {
            int m = bm + wm + mi * 16 + rr * 8 + gid;
            float rowpart = 0.f;    // OUT==3 row sum
            float invr = 1.f;       // OUT==4 reciprocal denominator
            if (OUT == 4) {
                invr = 1.0f / ((const float*)Cv)[(size_t)bz * NSEQ + m];
            }
            #pragma unroll
            for (int ni = 0; ni < 4; ni++) {
                int n0 = bn + wn + ni * 8 + tg * 2;
                #pragma unroll
                for (int cc = 0; cc < 2; cc++) {
                    int n = n0 + cc;
                    if (n < Nn) {
                        float v = acc[mi][ni][rr * 2 + cc] * alpha;
                        if (BIAS) v += bias[n];
                        if (GELU) v = 0.5f * v * (1.0f + erff(v * 0.70710678118654752f));
                        if (OUT == 0) {
                            ((float*)Cp)[coff + (size_t)m * ldc + n] = v;
                        } else if (OUT == 1) {
                            ((bf16*)Cp)[coff + (size_t)m * ldc + n] = __float2bfloat16_rn(v);
                        } else if (OUT == 2) {
                            if (n < 2*INNERX) {
                                ((bf16*)Cp)[coff + (size_t)m * ldc + n] = __float2bfloat16_rn(v);
                            } else {
                                int c = n - 2*INNERX;
                                size_t vi = ((size_t)(m >> 1) * INNERX + c) * 2 + (m & 1);
                                ((bf16*)Cv)[vi] = __float2bfloat16_rn(v);
                            }
                        } else if (OUT == 3) {
                            float e = __expf(fminf(v, 80.f));
                            rowpart += e;
                            ((bf16*)Cp)[coff + (size_t)m * ldc + n] = __float2bfloat16_rn(e);
                        } else { // OUT == 4
                            ((bf16*)Cp)[coff + (size_t)m * ldc + n] = __float2bfloat16_rn(v * invr);
                        }
                    }
                }
            }
            if (OUT == 3) {
                // reduce across the 4 tg-lanes of this row (lanes gid*4 + tg)
                rowpart += __shfl_down_sync(0xffffffffu, rowpart, 1, 4);
                rowpart += __shfl_down_sync(0xffffffffu, rowpart, 2, 4);
                if (tg == 0)
                    atomicAdd(&((float*)Cv)[(size_t)bz * NSEQ + m], rowpart);
            }
        }
    }
}

// ---------------- host orchestration ----------------
extern "C" void kernel_launch(void* const* d_in, const int* in_sizes, int n_in,
                              void* d_out, int out_size) {
    const float* x         = (const float*)d_in[0];
    const float* gam_a     = (const float*)d_in[1];
    const float* Wq        = (const float*)d_in[2];
    const float* Wk        = (const float*)d_in[3];
    const float* Wv        = (const float*)d_in[4];
    const float* Wo        = (const float*)d_in[5];
    const float* gam_m     = (const float*)d_in[6];
    const float* W1        = (const float*)d_in[7];
    const float* b1        = (const float*)d_in[8];
    const float* W2        = (const float*)d_in[9];
    const float* b2        = (const float*)d_in[10];
    const float* gam_mid   = (const float*)d_in[11];
    const float* gam_final = (const float*)d_in[12];
    float* out = (float*)d_out;

    float *px, *ppart, *prsum;
    bf16 *ph, *pqk, *po, *psim, *pmh;
    uint32_t *pv, *pwqkv, *pwo, *pw1, *pw2;
    cudaGetSymbolAddress((void**)&px,    g_x);
    cudaGetSymbolAddress((void**)&ph,    g_h);
    cudaGetSymbolAddress((void**)&pqk,   g_qk);
    cudaGetSymbolAddress((void**)&pv,    g_v);
    cudaGetSymbolAddress((void**)&po,    g_o);
    cudaGetSymbolAddress((void**)&psim,  g_sim);
    cudaGetSymbolAddress((void**)&pmh,   g_mh);
    cudaGetSymbolAddress((void**)&ppart, g_part);
    cudaGetSymbolAddress((void**)&prsum, g_rsum);
    cudaGetSymbolAddress((void**)&pwqkv, g_wqkv);
    cudaGetSymbolAddress((void**)&pwo,   g_wo);
    cudaGetSymbolAddress((void**)&pw1,   g_w1);
    cudaGetSymbolAddress((void**)&pw2,   g_w2);

    cudaFuncSetAttribute(mma_gemm<false,false,false,false,2>,
                         cudaFuncAttributeMaxDynamicSharedMemorySize, SMEM_BYTES);
    cudaFuncSetAttribute(mma_gemm<true,false,false,false,3>,
                         cudaFuncAttributeMaxDynamicSharedMemorySize, SMEM_BYTES);
    cudaFuncSetAttribute(mma_gemm<false,false,false,false,4>,
                         cudaFuncAttributeMaxDynamicSharedMemorySize, SMEM_BYTES);
    cudaFuncSetAttribute(mma_gemm<false,false,false,true,0>,
                         cudaFuncAttributeMaxDynamicSharedMemorySize, SMEM_BYTES);
    cudaFuncSetAttribute(mma_gemm<false,true,true,false,1>,
                         cudaFuncAttributeMaxDynamicSharedMemorySize, SMEM_BYTES);

    // ---- fused weight packing + x copy (one node) ----
    pack_all_kernel<<<(unsigned)((NPACK + 255)/256), 256>>>(
        Wq, Wk, Wv, Wo, W1, W2, x, pwqkv, pwo, pw1, pw2, px);

    // first attention pre-norm (also zeros rsum)
    ln_kernel<<<ROWSX, DIMX>>>(px, gam_a + 0, ph);

    const long sQK_b  = (long)NSEQ * 2*INNERX;
    const long sQK_h  = (long)DHX;
    const long sSIM_h = (long)NSEQ * NSEQ;
    const long sSIM_b = sSIM_h * HEADSX;
    const long sV_b   = (long)(NSEQ/2) * INNERX;   // v words
    const long sV_h   = (long)DHX;
    const long sO_b   = (long)NSEQ * INNERX;
    const long sO_h   = (long)DHX;

    auto do_attn = [&](int widx) {
        const uint32_t* wqkv_l = pwqkv + (size_t)widx * (DIMX/2) * NQKV;
        const uint32_t* wo_l   = pwo   + (size_t)widx * (INNERX/2) * DIMX;
        // fused QKV: q,k -> pqk; v -> interleaved pv
        mma_gemm<false,false,false,false,2><<<dim3(NQKV/64, ROWSX/128, 1), 256, SMEM_BYTES>>>(
            ph, wqkv_l, nullptr, pqk, pv, ROWSX, NQKV, DIMX, DIMX, NQKV, 2*INNERX,
            0,0,0,0,0,0, 0, 1.0f);
        // scores + fused exp/rowsum: sim = exp(SCALE * q@k^T), rsum += row sums
        mma_gemm<true,false,false,false,3><<<dim3(NSEQ/64, NSEQ/128, BX*HEADSX), 256, SMEM_BYTES>>>(
            pqk, pqk + INNERX, nullptr, psim, (uint32_t*)prsum, NSEQ, NSEQ, DHX,
            2*INNERX, 2*INNERX, NSEQ,
            sQK_b, sQK_h, sQK_b, sQK_h, sSIM_b, sSIM_h, 0, SCALEX);
        // context = (exp @ v) / rsum per (b,h)
        mma_gemm<false,false,false,false,4><<<dim3(DHX/64, NSEQ/128, BX*HEADSX), 256, SMEM_BYTES>>>(
            psim, pv, nullptr, po, (uint32_t*)prsum, NSEQ, DHX, NSEQ,
            NSEQ, INNERX /*words*/, INNERX,
            sSIM_b, sSIM_h, sV_b, sV_h, sO_b, sO_h, 0, 1.0f);
        // Wo split-K partials (fp32), N=96 -> 2 n-tiles
        mma_gemm<false,false,false,true,0><<<dim3(2, ROWSX/128, SPLIT_WO), 256, SMEM_BYTES>>>(
            po, wo_l, nullptr, ppart, nullptr, ROWSX, DIMX, INNERX/SPLIT_WO,
            INNERX, DIMX /*words*/, DIMX,
            0,0,0,0,0,0, (long)ROWSX*DIMX, 1.0f);
    };
    auto do_mlp_gemms = [&](int midx) {
        const uint32_t* w1_l = pw1 + (size_t)midx * (DIMX/2) * HIDX;
        const uint32_t* w2_l = pw2 + (size_t)midx * (HIDX/2) * DIMX;
        mma_gemm<false,true,true,false,1><<<dim3(HIDX/64, ROWSX/128, 1), 256, SMEM_BYTES>>>(
            ph, w1_l, b1 + (size_t)midx * HIDX, pmh, nullptr, ROWSX, HIDX, DIMX,
            DIMX, HIDX /*words*/, HIDX,
            0,0,0,0,0,0, 0, 1.0f);
        mma_gemm<false,false,false,true,0><<<dim3(2, ROWSX/128, SPLIT_W2), 256, SMEM_BYTES>>>(
            pmh, w2_l, nullptr, ppart, nullptr, ROWSX, DIMX, HIDX/SPLIT_W2,
            HIDX, DIMX /*words*/, DIMX,
            0,0,0,0,0,0, (long)ROWSX*DIMX, 1.0f);
    };

    for (int d = 0; d < DEPTHX; d++) {
        do_attn(3*d + 0);
        red_ln_kernel<true,false><<<ROWSX, DIMX>>>(
            ppart, SPLIT_WO, nullptr, px, gam_m + (size_t)(2*d+0)*DIMX, ph);
        do_mlp_gemms(2*d + 0);
        red_ln_kernel<true,true><<<ROWSX, DIMX>>>(
            ppart, SPLIT_W2, b2 + (size_t)(2*d+0)*DIMX, px, gam_a + (size_t)(3*d+1)*DIMX, ph);
        do_attn(3*d + 1);
        red_ln_kernel<true,false><<<ROWSX, DIMX>>>(
            ppart, SPLIT_WO, nullptr, px, gam_a + (size_t)(3*d+2)*DIMX, ph);
        do_attn(3*d + 2);
        // fused: reduce + bare mid-LN + MLP pre-norm
        red_ln_mid_kernel<<<ROWSX, DIMX>>>(
            ppart, SPLIT_WO, px, gam_mid + (size_t)d*DIMX, gam_m + (size_t)(2*d+1)*DIMX, ph);
        do_mlp_gemms(2*d + 1);
        if (d < DEPTHX - 1) {
            red_ln_kernel<true,true><<<ROWSX, DIMX>>>(
                ppart, SPLIT_W2, b2 + (size_t)(2*d+1)*DIMX, px, gam_a + (size_t)(3*d+3)*DIMX, ph);
        } else {
            red_ln_kernel<false,true><<<ROWSX, DIMX>>>(
                ppart, SPLIT_W2, b2 + (size_t)(2*d+1)*DIMX, px, gam_final, out);
        }
    }
}